// round 6
// baseline (speedup 1.0000x reference)
#include <cuda_runtime.h>
#include <stdint.h>

// ---------------------------------------------------------------------------
// LogSqrt2Quantizer — single persistent fused kernel, unroll x4 for MLP.
//
// Math collapse: the whole reference chain
//   x_int = rint(x / s_x); y = rint(-log2(x_int + bias)) * c;
//   q = clip(rint(y/scale) + zp, 0, 15); out = lut[q] * s_x
// depends on x only through mp = rint(log2(v)), v = x_int + bias (an exact
// small integer in [66, 65602]). Each persistent block builds the 32-entry
// mp -> out table ONCE in shared memory with IEEE-exact fp32 ops
// (__fdiv_rn / rintf, flag-independent; verified rel_err == 0.0).
//
// mp is computed EXACTLY over the integer v:
//   n = floor(log2 v);  mp = n + (v*v >= 2^(2n+1))
// (ties impossible: 2^(n+0.5) irrational).
//
// v is formed as __float2int_rn(x * inv_sx) + int_bias: cvt.rni is
// round-half-even (== rintf/jnp.round), x * 2^16 is exact, and the integer
// add is exact — bit-identical to the fp32 sequence, 2 fewer ops.
//
// Unroll x4 with front-batched __ldcs raises per-thread MLP to 4, deepening
// the DRAM request queues (round-5 limiter: dram 78%, everything else idle).
// ---------------------------------------------------------------------------

__device__ __forceinline__ int lsq_mp(float x, float inv_sx, int ibias) {
    unsigned v = (unsigned)(__float2int_rn(x * inv_sx) + ibias);
    int n = 31 - __clz(v | 1u);                // |1 guards clz(0) only
    unsigned long long vv = (unsigned long long)v * (unsigned long long)v;
    return n + (int)(vv >> (2 * n + 1));       // 0 or 1
}

__global__ void __launch_bounds__(256, 4)
lsq_fused_kernel(const float4* __restrict__ in, float4* __restrict__ out,
                 const float* __restrict__ s_x_p,
                 const float* __restrict__ bias_p,
                 const float* __restrict__ minv_p,
                 const float* __restrict__ maxv_p,
                 const float* __restrict__ lut,
                 int n4, int n, int out_size) {
    __shared__ float s_tab[32];
    __shared__ float s_inv_sx;
    __shared__ int   s_ibias;

    const unsigned tid = threadIdx.x;

    // --- per-block prologue (once per persistent block, ~600 total) -------
    if (tid < 32) {
        const float sx = __ldg(s_x_p);
        const float mn = __ldg(minv_p);
        const float mx = __ldg(maxv_p);
        const float c  = 40342.0f;                       // rint(2^15.3)
        const float scale = __fdiv_rn(mx - mn, 15.0f);
        const float zp    = rintf(__fdiv_rn(-mn, scale));
        float y  = (float)(-(int)tid) * c;
        float qf = rintf(__fdiv_rn(y, scale)) + zp;
        qf = fminf(fmaxf(qf, 0.0f), 15.0f);
        s_tab[tid] = __ldg(&lut[(int)qf]) * sx;
        if (tid == 0) {
            s_inv_sx = __fdiv_rn(1.0f, sx);    // exact: s_x is a power of two
            s_ibias  = (int)__ldg(bias_p);     // bias is a small exact integer
        }
    } else if (tid < 64 && blockIdx.x == 0) {
        // Tuple tail: out[n .. out_size) = s_x (usually a single element).
        const float sx = __ldg(s_x_p);
        float* out_f = (float*)out;
        for (int j = n + (int)(tid - 32); j < out_size; j += 32)
            out_f[j] = sx;
    }
    __syncthreads();

    const float inv_sx = s_inv_sx;
    const int   ibias  = s_ibias;

    const int stride  = gridDim.x * blockDim.x;
    const int stride4 = stride << 2;
    int i = blockIdx.x * blockDim.x + tid;

    // --- main unrolled stream: 4 independent loads front-batched ----------
    for (; i + 3 * stride < n4; i += stride4) {
        float4 x0 = __ldcs(&in[i]);
        float4 x1 = __ldcs(&in[i + stride]);
        float4 x2 = __ldcs(&in[i + 2 * stride]);
        float4 x3 = __ldcs(&in[i + 3 * stride]);

        float4 r0, r1, r2, r3;
        r0.x = s_tab[lsq_mp(x0.x, inv_sx, ibias)];
        r0.y = s_tab[lsq_mp(x0.y, inv_sx, ibias)];
        r0.z = s_tab[lsq_mp(x0.z, inv_sx, ibias)];
        r0.w = s_tab[lsq_mp(x0.w, inv_sx, ibias)];
        r1.x = s_tab[lsq_mp(x1.x, inv_sx, ibias)];
        r1.y = s_tab[lsq_mp(x1.y, inv_sx, ibias)];
        r1.z = s_tab[lsq_mp(x1.z, inv_sx, ibias)];
        r1.w = s_tab[lsq_mp(x1.w, inv_sx, ibias)];
        r2.x = s_tab[lsq_mp(x2.x, inv_sx, ibias)];
        r2.y = s_tab[lsq_mp(x2.y, inv_sx, ibias)];
        r2.z = s_tab[lsq_mp(x2.z, inv_sx, ibias)];
        r2.w = s_tab[lsq_mp(x2.w, inv_sx, ibias)];
        r3.x = s_tab[lsq_mp(x3.x, inv_sx, ibias)];
        r3.y = s_tab[lsq_mp(x3.y, inv_sx, ibias)];
        r3.z = s_tab[lsq_mp(x3.z, inv_sx, ibias)];
        r3.w = s_tab[lsq_mp(x3.w, inv_sx, ibias)];

        __stcs(&out[i],              r0);
        __stcs(&out[i + stride],     r1);
        __stcs(&out[i + 2 * stride], r2);
        __stcs(&out[i + 3 * stride], r3);
    }

    // --- remainder ----------------------------------------------------------
    for (; i < n4; i += stride) {
        float4 x = __ldcs(&in[i]);
        float4 r;
        r.x = s_tab[lsq_mp(x.x, inv_sx, ibias)];
        r.y = s_tab[lsq_mp(x.y, inv_sx, ibias)];
        r.z = s_tab[lsq_mp(x.z, inv_sx, ibias)];
        r.w = s_tab[lsq_mp(x.w, inv_sx, ibias)];
        __stcs(&out[i], r);
    }
}

extern "C" void kernel_launch(void* const* d_in, const int* in_sizes, int n_in,
                              void* d_out, int out_size) {
    const float* x_hat = (const float*)d_in[0];
    const float* s_x   = (const float*)d_in[1];
    const float* bias  = (const float*)d_in[2];
    const float* minv  = (const float*)d_in[3];
    const float* maxv  = (const float*)d_in[4];
    const float* lut   = (const float*)d_in[5];
    float* out = (float*)d_out;

    const int n  = in_sizes[0];
    const int n4 = n >> 2;                     // N divisible by 4

    // Persistent launch: exactly one wave at 4 CTAs/SM on 152 SMs.
    const int threads = 256;
    int blocks = 152 * 4;
    const int max_blocks = (n4 + threads - 1) / threads;
    if (blocks > max_blocks) blocks = max_blocks;

    lsq_fused_kernel<<<blocks, threads>>>((const float4*)x_hat, (float4*)out,
                                          s_x, bias, minv, maxv, lut,
                                          n4, n, out_size);
}

// round 7
// speedup vs baseline: 1.0281x; 1.0281x over previous
#include <cuda_runtime.h>
#include <stdint.h>

// ---------------------------------------------------------------------------
// LogSqrt2Quantizer — single persistent fused kernel (round-5 shape) with a
// bit-trick exact log2-round.
//
// Math collapse: the reference chain depends on x only through
//   mp = round(log2(v)),  v = rint(x / s_x) + bias  (exact integer in
//   [66, 65602]).
// Each persistent block builds the 32-entry mp -> out table once in shared
// memory with IEEE-exact fp32 ops (__fdiv_rn / rintf; verified rel_err==0.0).
//
// mp bit trick: vf = rint(x * 2^16) + 66 is an exact fp32 integer, so its
// bits are ((n+127)<<23) | m with n = floor(log2 v). round(log2 v) = n +
// (m >= ceil(frac(sqrt2) * 2^23) = 3474676)  — the sqrt(2) mantissa pattern
// is exponent-independent, and ties are impossible (2^(n+.5) irrational).
// Adding K = 2^23 - 3474676 = 4913932 makes that test carry into the
// exponent field:
//     mp + 127 = (float_as_int(vf) + 4913932) >> 23
// This is bit-equivalent to the v*v >= 2^(2n+1) integer test verified in
// round 3, at 6 instructions/element instead of ~10.
//
// Round-6 lesson: DRAM ~78% is the effective mixed r/w ceiling; more MLP at
// lower occupancy REGRESSED. Keep 8 CTAs/SM, 256 threads, no manual unroll.
// ---------------------------------------------------------------------------

__device__ __forceinline__ int lsq_idx(float x, float inv_sx, float biasf) {
    float vf = rintf(x * inv_sx) + biasf;          // exact integer in fp32
    return (__float_as_int(vf) + 4913932) >> 23;   // = mp + 127
}

__global__ void __launch_bounds__(256, 8)
lsq_fused_kernel(const float4* __restrict__ in, float4* __restrict__ out,
                 const float* __restrict__ s_x_p,
                 const float* __restrict__ bias_p,
                 const float* __restrict__ minv_p,
                 const float* __restrict__ maxv_p,
                 const float* __restrict__ lut,
                 int n4, int n, int out_size) {
    __shared__ float s_tab[32];                    // indexed by mp+127-121
    __shared__ float s_inv_sx;
    __shared__ float s_biasf;

    const unsigned tid = threadIdx.x;

    // --- per-block prologue (once per persistent block, ~1.2K total) ------
    // Table covers mp in [0,31]; hot-path index is mp+127, rebased by -127
    // at the lookup (folded into the LDS address constant).
    if (tid < 32) {
        const float sx = __ldg(s_x_p);
        const float mn = __ldg(minv_p);
        const float mx = __ldg(maxv_p);
        const float c  = 40342.0f;                       // rint(2^15.3)
        const float scale = __fdiv_rn(mx - mn, 15.0f);
        const float zp    = rintf(__fdiv_rn(-mn, scale));
        float y  = (float)(-(int)tid) * c;
        float qf = rintf(__fdiv_rn(y, scale)) + zp;
        qf = fminf(fmaxf(qf, 0.0f), 15.0f);
        s_tab[tid] = __ldg(&lut[(int)qf]) * sx;
        if (tid == 0) {
            s_inv_sx = __fdiv_rn(1.0f, sx);    // exact: s_x is a power of two
            s_biasf  = __ldg(bias_p);          // 66.0f (exact small integer)
        }
    } else if (tid < 64 && blockIdx.x == 0) {
        // Tuple tail: out[n .. out_size) = s_x (usually a single element).
        const float sx = __ldg(s_x_p);
        float* out_f = (float*)out;
        for (int j = n + (int)(tid - 32); j < out_size; j += 32)
            out_f[j] = sx;
    }
    __syncthreads();

    const float inv_sx = s_inv_sx;
    const float biasf  = s_biasf;
    // Rebase so hot-path index (mp+127) hits s_tab directly.
    const float* tabm = s_tab - 127;

    // --- persistent grid-stride stream ------------------------------------
    const int stride = gridDim.x * blockDim.x;
    for (int i = blockIdx.x * blockDim.x + tid; i < n4; i += stride) {
        float4 x = __ldcs(&in[i]);             // evict-first: pure stream
        float4 r;
        r.x = tabm[lsq_idx(x.x, inv_sx, biasf)];
        r.y = tabm[lsq_idx(x.y, inv_sx, biasf)];
        r.z = tabm[lsq_idx(x.z, inv_sx, biasf)];
        r.w = tabm[lsq_idx(x.w, inv_sx, biasf)];
        __stcs(&out[i], r);
    }
}

extern "C" void kernel_launch(void* const* d_in, const int* in_sizes, int n_in,
                              void* d_out, int out_size) {
    const float* x_hat = (const float*)d_in[0];
    const float* s_x   = (const float*)d_in[1];
    const float* bias  = (const float*)d_in[2];
    const float* minv  = (const float*)d_in[3];
    const float* maxv  = (const float*)d_in[4];
    const float* lut   = (const float*)d_in[5];
    float* out = (float*)d_out;

    const int n  = in_sizes[0];
    const int n4 = n >> 2;                     // N divisible by 4

    // Persistent launch: 8 CTAs per SM on GB300's 152 SMs (round-5 shape).
    const int threads = 256;
    int blocks = 152 * 8;
    const int max_blocks = (n4 + threads - 1) / threads;
    if (blocks > max_blocks) blocks = max_blocks;

    lsq_fused_kernel<<<blocks, threads>>>((const float4*)x_hat, (float4*)out,
                                          s_x, bias, minv, maxv, lut,
                                          n4, n, out_size);
}

// round 8
// speedup vs baseline: 1.0427x; 1.0142x over previous
#include <cuda_runtime.h>
#include <stdint.h>

// ---------------------------------------------------------------------------
// LogSqrt2Quantizer — persistent fused kernel, bit-trick exact log2-round,
// unroll x2 at FULL occupancy (round-7 math, +MLP without the round-6
// occupancy sacrifice).
//
// Math collapse: the reference chain depends on x only through
//   mp = round(log2(v)),  v = rint(x / s_x) + bias  (exact integer in
//   [66, 65602]).
// Each persistent block builds the 32-entry mp -> out table once in shared
// memory with IEEE-exact fp32 ops (__fdiv_rn / rintf; rel_err == 0.0
// verified rounds 3/5/6/7).
//
// mp bit trick: vf = rint(x * 2^16) + 66 is an exact fp32 integer, so its
// bits are ((n+127)<<23) | m with n = floor(log2 v). round(log2 v) = n +
// (m >= ceil(frac(sqrt2) * 2^23) = 3474676); the sqrt(2) mantissa threshold
// is exponent-independent and ties are impossible. Adding
// K = 2^23 - 3474676 = 4913932 carries that test into the exponent field:
//     mp + 127 = (float_as_int(vf) + 4913932) >> 23
// (bit-equivalent to the verified v*v >= 2^(2n+1) integer test).
//
// Lessons kept: DRAM ~79% is the binding pipe; occupancy 8 CTA/SM must not
// drop (round 6); regs must stay <= 32 under __launch_bounds__(256, 8).
// ---------------------------------------------------------------------------

__device__ __forceinline__ int lsq_idx(float x, float inv_sx, float biasf) {
    float vf = rintf(x * inv_sx) + biasf;          // exact integer in fp32
    return (__float_as_int(vf) + 4913932) >> 23;   // = mp + 127
}

__global__ void __launch_bounds__(256, 8)
lsq_fused_kernel(const float4* __restrict__ in, float4* __restrict__ out,
                 const float* __restrict__ s_x_p,
                 const float* __restrict__ bias_p,
                 const float* __restrict__ minv_p,
                 const float* __restrict__ maxv_p,
                 const float* __restrict__ lut,
                 int n4, int n, int out_size) {
    __shared__ float s_tab[32];
    __shared__ float s_inv_sx;
    __shared__ float s_biasf;

    const unsigned tid = threadIdx.x;

    // --- per-block prologue (once per persistent block, ~1.2K total) ------
    if (tid < 32) {
        const float sx = __ldg(s_x_p);
        const float mn = __ldg(minv_p);
        const float mx = __ldg(maxv_p);
        const float c  = 40342.0f;                       // rint(2^15.3)
        const float scale = __fdiv_rn(mx - mn, 15.0f);
        const float zp    = rintf(__fdiv_rn(-mn, scale));
        float y  = (float)(-(int)tid) * c;
        float qf = rintf(__fdiv_rn(y, scale)) + zp;
        qf = fminf(fmaxf(qf, 0.0f), 15.0f);
        s_tab[tid] = __ldg(&lut[(int)qf]) * sx;
        if (tid == 0) {
            s_inv_sx = __fdiv_rn(1.0f, sx);    // exact: s_x is a power of two
            s_biasf  = __ldg(bias_p);          // 66.0f (exact small integer)
        }
    } else if (tid < 64 && blockIdx.x == 0) {
        // Tuple tail: out[n .. out_size) = s_x (usually a single element).
        const float sx = __ldg(s_x_p);
        float* out_f = (float*)out;
        for (int j = n + (int)(tid - 32); j < out_size; j += 32)
            out_f[j] = sx;
    }
    __syncthreads();

    const float inv_sx = s_inv_sx;
    const float biasf  = s_biasf;
    const float* tabm = s_tab - 127;           // rebase: index is mp+127

    const int stride  = gridDim.x * blockDim.x;
    const int stride2 = stride << 1;
    int i = blockIdx.x * blockDim.x + tid;

    // --- unroll x2: two independent front-batched LDG.128 per iteration ---
    for (; i + stride < n4; i += stride2) {
        float4 x0 = __ldcs(&in[i]);
        float4 x1 = __ldcs(&in[i + stride]);

        float4 r0, r1;
        r0.x = tabm[lsq_idx(x0.x, inv_sx, biasf)];
        r0.y = tabm[lsq_idx(x0.y, inv_sx, biasf)];
        r0.z = tabm[lsq_idx(x0.z, inv_sx, biasf)];
        r0.w = tabm[lsq_idx(x0.w, inv_sx, biasf)];
        r1.x = tabm[lsq_idx(x1.x, inv_sx, biasf)];
        r1.y = tabm[lsq_idx(x1.y, inv_sx, biasf)];
        r1.z = tabm[lsq_idx(x1.z, inv_sx, biasf)];
        r1.w = tabm[lsq_idx(x1.w, inv_sx, biasf)];

        __stcs(&out[i],          r0);
        __stcs(&out[i + stride], r1);
    }

    // --- remainder ---------------------------------------------------------
    for (; i < n4; i += stride) {
        float4 x = __ldcs(&in[i]);
        float4 r;
        r.x = tabm[lsq_idx(x.x, inv_sx, biasf)];
        r.y = tabm[lsq_idx(x.y, inv_sx, biasf)];
        r.z = tabm[lsq_idx(x.z, inv_sx, biasf)];
        r.w = tabm[lsq_idx(x.w, inv_sx, biasf)];
        __stcs(&out[i], r);
    }
}

extern "C" void kernel_launch(void* const* d_in, const int* in_sizes, int n_in,
                              void* d_out, int out_size) {
    const float* x_hat = (const float*)d_in[0];
    const float* s_x   = (const float*)d_in[1];
    const float* bias  = (const float*)d_in[2];
    const float* minv  = (const float*)d_in[3];
    const float* maxv  = (const float*)d_in[4];
    const float* lut   = (const float*)d_in[5];
    float* out = (float*)d_out;

    const int n  = in_sizes[0];
    const int n4 = n >> 2;                     // N divisible by 4

    // Persistent launch: 8 CTAs per SM on GB300's 152 SMs.
    const int threads = 256;
    int blocks = 152 * 8;
    const int max_blocks = (n4 + threads - 1) / threads;
    if (blocks > max_blocks) blocks = max_blocks;

    lsq_fused_kernel<<<blocks, threads>>>((const float4*)x_hat, (float4*)out,
                                          s_x, bias, minv, maxv, lut,
                                          n4, n, out_size);
}